// round 3
// baseline (speedup 1.0000x reference)
#include <cuda_runtime.h>

// Problem constants
#define B_  8
#define S_  512
#define D_  1024
#define V_  32000
#define ND_ 8

// Scratch for hidden = hs @ W_base + b_base : [B*S, D] fp32 = 16 MB
__device__ __align__(16) float g_hidden[B_ * S_ * D_];

// ---------------------------------------------------------------------------
// Classic 128x128x8 register-tiled SGEMM body.
// A: [*, K] row-major (stride K), Bm: [K, N] row-major, bias: [N], C: [*, N].
// 256 threads, each computes an 8x8 microtile.
// ---------------------------------------------------------------------------
__device__ __forceinline__ void sgemm_body(
    const float* __restrict__ A,
    const float* __restrict__ Bm,
    const float* __restrict__ bias,
    float* __restrict__ C,
    int K, int N, int m0, int n0)
{
    __shared__ float As[8][128];
    __shared__ float Bs[8][128];

    const int t  = threadIdx.x;     // 0..255
    const int tx = t & 15;          // N-dir thread coord (0..15)
    const int ty = t >> 4;          // M-dir thread coord (0..15)

    float acc[8][8];
    #pragma unroll
    for (int i = 0; i < 8; i++)
        #pragma unroll
        for (int j = 0; j < 8; j++) acc[i][j] = 0.0f;

    // A-tile load mapping: 128 rows x 8 k = 256 float4
    const int aRow = t >> 1;            // 0..127
    const int aK4  = (t & 1) * 4;       // 0 or 4
    // B-tile load mapping: 8 rows x 128 cols = 256 float4
    const int bK   = t >> 5;            // 0..7
    const int bN4  = (t & 31) * 4;      // 0..124

    const float* Aptr = A + (size_t)(m0 + aRow) * K + aK4;
    const float* Bptr = Bm + (size_t)bK * N + n0 + bN4;

    for (int k0 = 0; k0 < K; k0 += 8) {
        float4 av = *reinterpret_cast<const float4*>(Aptr);
        float4 bv = *reinterpret_cast<const float4*>(Bptr);
        __syncthreads();   // previous iteration's smem reads done
        As[aK4 + 0][aRow] = av.x;
        As[aK4 + 1][aRow] = av.y;
        As[aK4 + 2][aRow] = av.z;
        As[aK4 + 3][aRow] = av.w;
        *reinterpret_cast<float4*>(&Bs[bK][bN4]) = bv;
        __syncthreads();
        Aptr += 8;
        Bptr += (size_t)8 * N;

        #pragma unroll
        for (int kk = 0; kk < 8; kk++) {
            float a[8], b[8];
            #pragma unroll
            for (int i = 0; i < 8; i++) a[i] = As[kk][ty * 8 + i];
            #pragma unroll
            for (int j = 0; j < 8; j++) b[j] = Bs[kk][tx * 8 + j];
            #pragma unroll
            for (int i = 0; i < 8; i++)
                #pragma unroll
                for (int j = 0; j < 8; j++)
                    acc[i][j] = fmaf(a[i], b[j], acc[i][j]);
        }
    }

    // Epilogue: add bias, vectorized stores
    #pragma unroll
    for (int i = 0; i < 8; i++) {
        const int row = m0 + ty * 8 + i;
        float* crow = C + (size_t)row * N + n0 + tx * 8;
        const float* brow = bias + n0 + tx * 8;
        #pragma unroll
        for (int j = 0; j < 8; j += 4) {
            float4 v;
            v.x = acc[i][j + 0] + brow[j + 0];
            v.y = acc[i][j + 1] + brow[j + 1];
            v.z = acc[i][j + 2] + brow[j + 2];
            v.w = acc[i][j + 3] + brow[j + 3];
            *reinterpret_cast<float4*>(crow + j) = v;
        }
    }
}

// ---------------------------------------------------------------------------
// Kernel A: hidden = hidden_states @ W_base + b_base
// grid: (N/128 = 8, M/128 = 32), block 256
// ---------------------------------------------------------------------------
__global__ __launch_bounds__(256) void base_proj_kernel(
    const float* __restrict__ hs,      // [B*S, D]
    const float* __restrict__ Wb,      // [D, D]
    const float* __restrict__ bb)      // [D]
{
    const int n0 = blockIdx.x * 128;
    const int m0 = blockIdx.y * 128;
    sgemm_body(hs, Wb, bb, g_hidden, D_, D_, m0, n0);
}

// ---------------------------------------------------------------------------
// Kernel B: out[b] = hidden[b] @ W_heads[idx[b]] + b_heads[idx[b]]
// grid: (V/128 = 250, S/128 = 4, B = 8), block 256
// ---------------------------------------------------------------------------
__global__ __launch_bounds__(256) void heads_kernel(
    const int*   __restrict__ domain_ids,  // [B]
    const float* __restrict__ W_heads,     // [ND+1, D, V]
    const float* __restrict__ b_heads,     // [ND+1, V]
    float* __restrict__ out)               // [B, S, V]
{
    const int b = blockIdx.z;
    int id = domain_ids[b];
    const int idx = (id >= 0 && id < ND_) ? id : ND_;

    const float* A    = g_hidden + (size_t)b * S_ * D_;
    const float* Bm   = W_heads + (size_t)idx * D_ * V_;
    const float* bias = b_heads + (size_t)idx * V_;
    float* C          = out + (size_t)b * S_ * V_;

    const int n0 = blockIdx.x * 128;
    const int m0 = blockIdx.y * 128;
    sgemm_body(A, Bm, bias, C, D_, V_, m0, n0);
}

// ---------------------------------------------------------------------------
// Launch
// inputs (metadata order): hidden_states f32, domain_ids i32, W_base f32,
//                          b_base f32, W_heads f32, b_heads f32
// ---------------------------------------------------------------------------
extern "C" void kernel_launch(void* const* d_in, const int* in_sizes, int n_in,
                              void* d_out, int out_size)
{
    const float* hs      = (const float*)d_in[0];
    const int*   dom     = (const int*)  d_in[1];
    const float* W_base  = (const float*)d_in[2];
    const float* b_base  = (const float*)d_in[3];
    const float* W_heads = (const float*)d_in[4];
    const float* b_heads = (const float*)d_in[5];
    float* out = (float*)d_out;

    dim3 gridA(D_ / 128, (B_ * S_) / 128);    // (8, 32)
    base_proj_kernel<<<gridA, 256>>>(hs, W_base, b_base);

    dim3 gridB(V_ / 128, S_ / 128, B_);       // (250, 4, 8)
    heads_kernel<<<gridB, 256>>>(dom, W_heads, b_heads, out);
}

// round 5
// speedup vs baseline: 3.7645x; 3.7645x over previous
#include <cuda_runtime.h>
#include <cstdint>

#define B_  8
#define S_  512
#define D_  1024
#define V_  32000
#define ND_ 8

#define BM 256
#define BN 128
#define BK 32
#define NCHUNK (D_ / BK)        // 32

#define ASTRIDE_F 36            // floats per smem row (32 data + 4 pad) = 144 B
#define A_STAGE_B (BM * ASTRIDE_F * 4)   // 36864 B
#define B_STAGE_B (BN * ASTRIDE_F * 4)   // 18432 B
#define OFF_A0 0
#define OFF_A1 A_STAGE_B
#define OFF_B0 (2 * A_STAGE_B)
#define OFF_B1 (2 * A_STAGE_B + B_STAGE_B)
#define SMEM_TOTAL (2 * A_STAGE_B + 2 * B_STAGE_B)   // 110592 B

__device__ float g_hidden[B_ * S_ * D_];   // RN-tf32 base-proj output
__device__ float g_hs_rnd[B_ * S_ * D_];   // RN-tf32 hidden_states

// ---------------- helpers ----------------
__device__ __forceinline__ uint32_t smem_u32(const void* p) {
    uint32_t a;
    asm("{ .reg .u64 t; cvta.to.shared.u64 t, %1; cvt.u32.u64 %0, t; }" : "=r"(a) : "l"(p));
    return a;
}
__device__ __forceinline__ float to_tf32(float x) {
    float y; asm("cvt.rna.tf32.f32 %0, %1;" : "=f"(y) : "f"(x)); return y;
}
__device__ __forceinline__ void cp16(uint32_t d, const float* s) {
    asm volatile("cp.async.cg.shared.global [%0], [%1], 16;" :: "r"(d), "l"(s));
}
__device__ __forceinline__ void ldsm_x4(uint32_t* r, uint32_t addr) {
    asm volatile("ldmatrix.sync.aligned.m8n8.x4.shared.b16 {%0,%1,%2,%3}, [%4];"
                 : "=r"(r[0]), "=r"(r[1]), "=r"(r[2]), "=r"(r[3]) : "r"(addr));
}
__device__ __forceinline__ void mma_tf32(float* d, const uint32_t* a, const uint32_t* b) {
    asm volatile(
        "mma.sync.aligned.m16n8k8.row.col.f32.tf32.tf32.f32 "
        "{%0,%1,%2,%3}, {%4,%5,%6,%7}, {%8,%9}, {%0,%1,%2,%3};"
        : "+f"(d[0]), "+f"(d[1]), "+f"(d[2]), "+f"(d[3])
        : "r"(a[0]), "r"(a[1]), "r"(a[2]), "r"(a[3]), "r"(b[0]), "r"(b[1]));
}

// ---------------------------------------------------------------------------
// C[m0:m0+256, n0:n0+128] = A[m0:, :1024] @ B[:1024, n0:] + bias
// A row stride = D_ (1024), B row stride = Nld. All operands in A are assumed
// already RN-tf32; B is RN-rounded in the transpose path here.
// ---------------------------------------------------------------------------
__device__ __forceinline__ void gemm_tile(
    const float* __restrict__ A,
    const float* __restrict__ Bsrc,
    const float* __restrict__ bias,
    float* __restrict__ C,
    int Nld, int m0, int n0, bool round_out)
{
    extern __shared__ char smem[];
    const uint32_t sb = smem_u32(smem);

    const int t    = threadIdx.x;
    const int lane = t & 31;
    const int wid  = t >> 5;
    const int wm   = wid >> 1;       // 0..3 : warp m position (64 rows each)
    const int wn   = wid & 1;        // 0..1 : warp n position (64 cols each)

    // B transpose mapping: thread handles column n=bn, k-rows [bk0, bk0+16)
    const int bn  = t & 127;
    const int bk0 = (t >> 7) * 16;

    float acc[4][8][4];
    #pragma unroll
    for (int mt = 0; mt < 4; mt++)
        #pragma unroll
        for (int nt = 0; nt < 8; nt++)
            #pragma unroll
            for (int r = 0; r < 4; r++) acc[mt][nt][r] = 0.0f;

    // ---- prologue: stage chunk 0 ----
    float vpre[16];
    {
        #pragma unroll
        for (int i = 0; i < 8; i++) {
            const int idx = i * 256 + t;
            const int row = idx >> 3, q = idx & 7;
            cp16(sb + OFF_A0 + row * 144 + q * 16,
                 A + (size_t)(m0 + row) * D_ + q * 4);
        }
        asm volatile("cp.async.commit_group;" ::: "memory");

        const float* p = Bsrc + (size_t)bk0 * Nld + n0 + bn;
        #pragma unroll
        for (int kk = 0; kk < 16; kk++) vpre[kk] = p[(size_t)kk * Nld];

        const uint32_t dst = sb + OFF_B0 + bn * 144 + bk0 * 4;
        #pragma unroll
        for (int q = 0; q < 4; q++) {
            asm volatile("st.shared.v4.b32 [%0], {%1,%2,%3,%4};" :: "r"(dst + q * 16),
                "r"(__float_as_uint(to_tf32(vpre[4*q+0]))),
                "r"(__float_as_uint(to_tf32(vpre[4*q+1]))),
                "r"(__float_as_uint(to_tf32(vpre[4*q+2]))),
                "r"(__float_as_uint(to_tf32(vpre[4*q+3]))) : "memory");
        }
        asm volatile("cp.async.wait_group 0;" ::: "memory");
        __syncthreads();
    }

    // ---- mainloop ----
    for (int c = 0; c < NCHUNK; c++) {
        const int buf = c & 1;
        const bool has_next = (c + 1 < NCHUNK);

        if (has_next) {
            // prefetch A(c+1) via cp.async into other buffer
            const uint32_t adst = sb + (buf ? OFF_A0 : OFF_A1);
            const int k0n = (c + 1) * BK;
            #pragma unroll
            for (int i = 0; i < 8; i++) {
                const int idx = i * 256 + t;
                const int row = idx >> 3, q = idx & 7;
                cp16(adst + row * 144 + q * 16,
                     A + (size_t)(m0 + row) * D_ + k0n + q * 4);
            }
            asm volatile("cp.async.commit_group;" ::: "memory");
            // prefetch B(c+1) into registers
            const float* p = Bsrc + (size_t)(k0n + bk0) * Nld + n0 + bn;
            #pragma unroll
            for (int kk = 0; kk < 16; kk++) vpre[kk] = p[(size_t)kk * Nld];
        }

        // compute chunk c from buf
        const uint32_t aBase = sb + (buf ? OFF_A1 : OFF_A0);
        const uint32_t bBase = sb + (buf ? OFF_B1 : OFF_B0);

        #pragma unroll
        for (int ks = 0; ks < 4; ks++) {
            uint32_t afr[4][4], bfr[4][4];
            #pragma unroll
            for (int mt = 0; mt < 4; mt++) {
                const int row = wm * 64 + mt * 16 + (lane & 15);
                ldsm_x4(afr[mt], aBase + row * 144 + ks * 32 + (lane >> 4) * 16);
            }
            const int sel = lane >> 3, j = lane & 7;
            #pragma unroll
            for (int p = 0; p < 4; p++) {
                const int row = wn * 64 + p * 16 + j + ((sel >= 2) ? 8 : 0);
                ldsm_x4(bfr[p], bBase + row * 144 + ks * 32 + (sel & 1) * 16);
            }
            #pragma unroll
            for (int mt = 0; mt < 4; mt++)
                #pragma unroll
                for (int p = 0; p < 4; p++) {
                    mma_tf32(acc[mt][2*p+0], afr[mt], &bfr[p][0]);
                    mma_tf32(acc[mt][2*p+1], afr[mt], &bfr[p][2]);
                }
        }

        if (has_next) {
            // store B(c+1) into other buffer (RN tf32)
            const uint32_t bdst = sb + (buf ? OFF_B0 : OFF_B1) + bn * 144 + bk0 * 4;
            #pragma unroll
            for (int q = 0; q < 4; q++) {
                asm volatile("st.shared.v4.b32 [%0], {%1,%2,%3,%4};" :: "r"(bdst + q * 16),
                    "r"(__float_as_uint(to_tf32(vpre[4*q+0]))),
                    "r"(__float_as_uint(to_tf32(vpre[4*q+1]))),
                    "r"(__float_as_uint(to_tf32(vpre[4*q+2]))),
                    "r"(__float_as_uint(to_tf32(vpre[4*q+3]))) : "memory");
            }
            asm volatile("cp.async.wait_group 0;" ::: "memory");
        }
        __syncthreads();
    }

    // ---- epilogue ----
    const int gid = lane >> 2, tig = lane & 3;
    #pragma unroll
    for (int mt = 0; mt < 4; mt++) {
        const int r0 = m0 + wm * 64 + mt * 16 + gid;
        #pragma unroll
        for (int nt = 0; nt < 8; nt++) {
            const int col = n0 + wn * 64 + nt * 8 + tig * 2;
            const float2 bv = *reinterpret_cast<const float2*>(bias + col);
            float2 o0, o1;
            o0.x = acc[mt][nt][0] + bv.x;  o0.y = acc[mt][nt][1] + bv.y;
            o1.x = acc[mt][nt][2] + bv.x;  o1.y = acc[mt][nt][3] + bv.y;
            if (round_out) {
                o0.x = to_tf32(o0.x); o0.y = to_tf32(o0.y);
                o1.x = to_tf32(o1.x); o1.y = to_tf32(o1.y);
            }
            *reinterpret_cast<float2*>(C + (size_t)r0 * Nld + col) = o0;
            *reinterpret_cast<float2*>(C + (size_t)(r0 + 8) * Nld + col) = o1;
        }
    }
}

// ---------------- kernels ----------------
__global__ __launch_bounds__(256) void round_hs_kernel(const float* __restrict__ hs) {
    const int i = (blockIdx.x * 256 + threadIdx.x) * 4;
    float4 v = *reinterpret_cast<const float4*>(hs + i);
    v.x = to_tf32(v.x); v.y = to_tf32(v.y); v.z = to_tf32(v.z); v.w = to_tf32(v.w);
    *reinterpret_cast<float4*>(g_hs_rnd + i) = v;
}

__global__ __launch_bounds__(256, 1) void gemm_base_kernel(
    const float* __restrict__ Wb, const float* __restrict__ bb)
{
    gemm_tile(g_hs_rnd, Wb, bb, g_hidden, D_,
              blockIdx.y * BM, blockIdx.x * BN, true);
}

__global__ __launch_bounds__(256, 1) void gemm_heads_kernel(
    const int* __restrict__ dom, const float* __restrict__ Wh,
    const float* __restrict__ bh, float* __restrict__ out)
{
    const int b = blockIdx.z;
    const int id = dom[b];
    const int idx = (id >= 0 && id < ND_) ? id : ND_;
    gemm_tile(g_hidden + (size_t)b * S_ * D_,
              Wh + (size_t)idx * D_ * V_,
              bh + (size_t)idx * V_,
              out + (size_t)b * S_ * V_,
              V_, blockIdx.y * BM, blockIdx.x * BN, false);
}

// ---------------- launch ----------------
extern "C" void kernel_launch(void* const* d_in, const int* in_sizes, int n_in,
                              void* d_out, int out_size)
{
    const float* hs      = (const float*)d_in[0];
    const int*   dom     = (const int*)  d_in[1];
    const float* W_base  = (const float*)d_in[2];
    const float* b_base  = (const float*)d_in[3];
    const float* W_heads = (const float*)d_in[4];
    const float* b_heads = (const float*)d_in[5];
    float* out = (float*)d_out;

    static bool attr_set = false;
    if (!attr_set) {
        cudaFuncSetAttribute(gemm_base_kernel,  cudaFuncAttributeMaxDynamicSharedMemorySize, SMEM_TOTAL);
        cudaFuncSetAttribute(gemm_heads_kernel, cudaFuncAttributeMaxDynamicSharedMemorySize, SMEM_TOTAL);
        attr_set = true;
    }

    round_hs_kernel<<<(B_ * S_ * D_) / (256 * 4), 256>>>(hs);

    dim3 gA(D_ / BN, (B_ * S_) / BM, 1);          // (8, 16, 1)
    gemm_base_kernel<<<gA, 256, SMEM_TOTAL>>>(W_base, b_base);

    dim3 gB(V_ / BN, S_ / BM, B_);                // (250, 2, 8)
    gemm_heads_kernel<<<gB, 256, SMEM_TOTAL>>>(dom, W_heads, b_heads, out);
}

// round 6
// speedup vs baseline: 5.5257x; 1.4678x over previous
#include <cuda_runtime.h>
#include <cuda_fp16.h>
#include <cstdint>

#define B_  8
#define S_  512
#define D_  1024
#define V_  32000
#define ND_ 8

#define BM 256
#define BN 128
#define BK 32
#define NCHUNK (D_ / BK)        // 32

#define ROWB 80                 // smem bytes per row: 64 data + 16 pad (conflict-free)
#define A_STAGE_B (BM * ROWB)   // 20480
#define B_STAGE_B (BN * ROWB)   // 10240
#define OFF_A0 0
#define OFF_A1 A_STAGE_B
#define OFF_B0 (2 * A_STAGE_B)
#define OFF_B1 (2 * A_STAGE_B + B_STAGE_B)
#define SMEM_TOTAL (2 * A_STAGE_B + 2 * B_STAGE_B)   // 61440

__device__ __half g_hidden[B_ * S_ * D_];   // fp16 base-proj output
__device__ __half g_hs_h[B_ * S_ * D_];     // fp16 hidden_states

// ---------------- helpers ----------------
__device__ __forceinline__ uint32_t smem_u32(const void* p) {
    uint32_t a;
    asm("{ .reg .u64 t; cvta.to.shared.u64 t, %1; cvt.u32.u64 %0, t; }" : "=r"(a) : "l"(p));
    return a;
}
// pack two fp32 -> f16x2 (lo = x, hi = y), round-to-nearest
__device__ __forceinline__ uint32_t pack_h2(float x, float y) {
    uint32_t d;
    asm("cvt.rn.f16x2.f32 %0, %2, %1;" : "=r"(d) : "f"(x), "f"(y));
    return d;
}
__device__ __forceinline__ void cp16(uint32_t d, const void* s) {
    asm volatile("cp.async.cg.shared.global [%0], [%1], 16;" :: "r"(d), "l"(s));
}
__device__ __forceinline__ void ldsm_x4(uint32_t* r, uint32_t addr) {
    asm volatile("ldmatrix.sync.aligned.m8n8.x4.shared.b16 {%0,%1,%2,%3}, [%4];"
                 : "=r"(r[0]), "=r"(r[1]), "=r"(r[2]), "=r"(r[3]) : "r"(addr));
}
__device__ __forceinline__ void mma_f16(float* d, const uint32_t* a, const uint32_t* b) {
    asm volatile(
        "mma.sync.aligned.m16n8k16.row.col.f32.f16.f16.f32 "
        "{%0,%1,%2,%3}, {%4,%5,%6,%7}, {%8,%9}, {%0,%1,%2,%3};"
        : "+f"(d[0]), "+f"(d[1]), "+f"(d[2]), "+f"(d[3])
        : "r"(a[0]), "r"(a[1]), "r"(a[2]), "r"(a[3]), "r"(b[0]), "r"(b[1]));
}

// ---------------------------------------------------------------------------
// C[m0:m0+256, n0:n0+128] = A[m0:, :1024] @ B[:1024, n0:] + bias
// A: fp16 [.., D_] row-major. B: fp32 [D_, Nld] (converted to fp16 in flight).
// HIDDEN_OUT: if true, write fp16 to Chalf instead of fp32 to C.
// ---------------------------------------------------------------------------
template <bool HIDDEN_OUT>
__device__ __forceinline__ void gemm_tile(
    const __half* __restrict__ A,
    const float*  __restrict__ Bsrc,
    const float*  __restrict__ bias,
    float* __restrict__ C, __half* __restrict__ Chalf,
    int Nld, int m0, int n0)
{
    extern __shared__ char smem[];
    const uint32_t sb = smem_u32(smem);

    const int t    = threadIdx.x;
    const int lane = t & 31;
    const int wid  = t >> 5;
    const int wm   = wid >> 1;       // 0..3
    const int wn   = wid & 1;        // 0..1

    // B transpose mapping: thread owns column n=bn, k-rows [bk0, bk0+16)
    const int bn  = t & 127;
    const int bk0 = (t >> 7) * 16;

    float acc[4][8][4];
    #pragma unroll
    for (int mt = 0; mt < 4; mt++)
        #pragma unroll
        for (int nt = 0; nt < 8; nt++)
            #pragma unroll
            for (int r = 0; r < 4; r++) acc[mt][nt][r] = 0.0f;

    float vpre[16];

    // ---- prologue: stage chunk 0 ----
    {
        #pragma unroll
        for (int i = 0; i < 4; i++) {
            const int idx = i * 256 + t;
            const int row = idx >> 2, q = idx & 3;       // q: 16B segment (8 halves)
            cp16(sb + OFF_A0 + row * ROWB + q * 16,
                 A + (size_t)(m0 + row) * D_ + q * 8);
        }
        asm volatile("cp.async.commit_group;" ::: "memory");

        const float* p = Bsrc + (size_t)bk0 * Nld + n0 + bn;
        #pragma unroll
        for (int kk = 0; kk < 16; kk++) vpre[kk] = p[(size_t)kk * Nld];

        uint32_t hw[8];
        #pragma unroll
        for (int j = 0; j < 8; j++) hw[j] = pack_h2(vpre[2*j], vpre[2*j+1]);
        const uint32_t dst = sb + OFF_B0 + bn * ROWB + bk0 * 2;
        asm volatile("st.shared.v4.b32 [%0], {%1,%2,%3,%4};" :: "r"(dst),
            "r"(hw[0]), "r"(hw[1]), "r"(hw[2]), "r"(hw[3]) : "memory");
        asm volatile("st.shared.v4.b32 [%0], {%1,%2,%3,%4};" :: "r"(dst + 16),
            "r"(hw[4]), "r"(hw[5]), "r"(hw[6]), "r"(hw[7]) : "memory");

        asm volatile("cp.async.wait_group 0;" ::: "memory");
        __syncthreads();
    }

    // ---- mainloop ----
    for (int c = 0; c < NCHUNK; c++) {
        const int buf = c & 1;
        const bool has_next = (c + 1 < NCHUNK);

        if (has_next) {
            const uint32_t adst = sb + (buf ? OFF_A0 : OFF_A1);
            const int k0n = (c + 1) * BK;
            #pragma unroll
            for (int i = 0; i < 4; i++) {
                const int idx = i * 256 + t;
                const int row = idx >> 2, q = idx & 3;
                cp16(adst + row * ROWB + q * 16,
                     A + (size_t)(m0 + row) * D_ + k0n + q * 8);
            }
            asm volatile("cp.async.commit_group;" ::: "memory");
            const float* p = Bsrc + (size_t)(k0n + bk0) * Nld + n0 + bn;
            #pragma unroll
            for (int kk = 0; kk < 16; kk++) vpre[kk] = p[(size_t)kk * Nld];
        }

        const uint32_t aBase = sb + (buf ? OFF_A1 : OFF_A0);
        const uint32_t bBase = sb + (buf ? OFF_B1 : OFF_B0);

        #pragma unroll
        for (int ks = 0; ks < 2; ks++) {           // two k16 steps per 32-k chunk
            uint32_t afr[4][4], bfr[4][4];
            // A fragments: rows m0..m15 (lanes 0-15), 16B col select by lane>>4
            #pragma unroll
            for (int mt = 0; mt < 4; mt++) {
                const int row = wm * 64 + mt * 16 + (lane & 15);
                ldsm_x4(afr[mt], aBase + row * ROWB + ks * 32 + (lane >> 4) * 16);
            }
            // B fragments: [n][k] rows; tiles (n0-7,k0-7),(n0-7,k8-15),(n8-15,k0-7),(n8-15,k8-15)
            #pragma unroll
            for (int p = 0; p < 4; p++) {
                const int nrow = wn * 64 + p * 16 + (lane & 7) + ((lane >> 4) ? 8 : 0);
                ldsm_x4(bfr[p], bBase + nrow * ROWB + ks * 32 + ((lane >> 3) & 1) * 16);
            }
            #pragma unroll
            for (int mt = 0; mt < 4; mt++)
                #pragma unroll
                for (int p = 0; p < 4; p++) {
                    mma_f16(acc[mt][2*p+0], afr[mt], &bfr[p][0]);
                    mma_f16(acc[mt][2*p+1], afr[mt], &bfr[p][2]);
                }
        }

        if (has_next) {
            uint32_t hw[8];
            #pragma unroll
            for (int j = 0; j < 8; j++) hw[j] = pack_h2(vpre[2*j], vpre[2*j+1]);
            const uint32_t dst = sb + (buf ? OFF_B0 : OFF_B1) + bn * ROWB + bk0 * 2;
            asm volatile("st.shared.v4.b32 [%0], {%1,%2,%3,%4};" :: "r"(dst),
                "r"(hw[0]), "r"(hw[1]), "r"(hw[2]), "r"(hw[3]) : "memory");
            asm volatile("st.shared.v4.b32 [%0], {%1,%2,%3,%4};" :: "r"(dst + 16),
                "r"(hw[4]), "r"(hw[5]), "r"(hw[6]), "r"(hw[7]) : "memory");
            asm volatile("cp.async.wait_group 0;" ::: "memory");
        }
        __syncthreads();
    }

    // ---- epilogue ----
    const int gid = lane >> 2, tig = lane & 3;
    #pragma unroll
    for (int mt = 0; mt < 4; mt++) {
        const int r0 = m0 + wm * 64 + mt * 16 + gid;
        #pragma unroll
        for (int nt = 0; nt < 8; nt++) {
            const int col = n0 + wn * 64 + nt * 8 + tig * 2;
            const float2 bv = *reinterpret_cast<const float2*>(bias + col);
            const float o0x = acc[mt][nt][0] + bv.x, o0y = acc[mt][nt][1] + bv.y;
            const float o1x = acc[mt][nt][2] + bv.x, o1y = acc[mt][nt][3] + bv.y;
            if (HIDDEN_OUT) {
                *reinterpret_cast<uint32_t*>(Chalf + (size_t)r0 * Nld + col)       = pack_h2(o0x, o0y);
                *reinterpret_cast<uint32_t*>(Chalf + (size_t)(r0 + 8) * Nld + col) = pack_h2(o1x, o1y);
            } else {
                *reinterpret_cast<float2*>(C + (size_t)r0 * Nld + col)       = make_float2(o0x, o0y);
                *reinterpret_cast<float2*>(C + (size_t)(r0 + 8) * Nld + col) = make_float2(o1x, o1y);
            }
        }
    }
}

// ---------------- kernels ----------------
__global__ __launch_bounds__(256) void round_hs_kernel(const float* __restrict__ hs) {
    const int i = (blockIdx.x * 256 + threadIdx.x) * 4;
    float4 v = *reinterpret_cast<const float4*>(hs + i);
    uint2 o;
    o.x = pack_h2(v.x, v.y);
    o.y = pack_h2(v.z, v.w);
    *reinterpret_cast<uint2*>(g_hs_h + i) = o;
}

__global__ __launch_bounds__(256, 1) void gemm_base_kernel(
    const float* __restrict__ Wb, const float* __restrict__ bb)
{
    gemm_tile<true>(g_hs_h, Wb, bb, nullptr, g_hidden, D_,
                    blockIdx.y * BM, blockIdx.x * BN);
}

__global__ __launch_bounds__(256, 1) void gemm_heads_kernel(
    const int* __restrict__ dom, const float* __restrict__ Wh,
    const float* __restrict__ bh, float* __restrict__ out)
{
    const int b = blockIdx.z;
    const int id = dom[b];
    const int idx = (id >= 0 && id < ND_) ? id : ND_;
    gemm_tile<false>(g_hidden + (size_t)b * S_ * D_,
                     Wh + (size_t)idx * D_ * V_,
                     bh + (size_t)idx * V_,
                     out + (size_t)b * S_ * V_, nullptr,
                     V_, blockIdx.y * BM, blockIdx.x * BN);
}

// ---------------- launch ----------------
extern "C" void kernel_launch(void* const* d_in, const int* in_sizes, int n_in,
                              void* d_out, int out_size)
{
    const float* hs      = (const float*)d_in[0];
    const int*   dom     = (const int*)  d_in[1];
    const float* W_base  = (const float*)d_in[2];
    const float* b_base  = (const float*)d_in[3];
    const float* W_heads = (const float*)d_in[4];
    const float* b_heads = (const float*)d_in[5];
    float* out = (float*)d_out;

    static bool attr_set = false;
    if (!attr_set) {
        cudaFuncSetAttribute(gemm_base_kernel,  cudaFuncAttributeMaxDynamicSharedMemorySize, SMEM_TOTAL);
        cudaFuncSetAttribute(gemm_heads_kernel, cudaFuncAttributeMaxDynamicSharedMemorySize, SMEM_TOTAL);
        attr_set = true;
    }

    round_hs_kernel<<<(B_ * S_ * D_) / (256 * 4), 256>>>(hs);

    dim3 gA(D_ / BN, (B_ * S_) / BM, 1);          // (8, 16, 1)
    gemm_base_kernel<<<gA, 256, SMEM_TOTAL>>>(W_base, b_base);

    dim3 gB(V_ / BN, S_ / BM, B_);                // (250, 2, 8)
    gemm_heads_kernel<<<gB, 256, SMEM_TOTAL>>>(dom, W_heads, b_heads, out);
}